// round 13
// baseline (speedup 1.0000x reference)
#include <cuda_runtime.h>

typedef unsigned long long ull;

// ---------------- packed f32x2 helpers (Blackwell FFMA2 path) ----------------
__device__ __forceinline__ ull pack2(float a, float b) {
    ull r; asm("mov.b64 %0, {%1,%2};" : "=l"(r) : "f"(a), "f"(b)); return r;
}
__device__ __forceinline__ float2 unpack2(ull v) {
    float2 f; asm("mov.b64 {%0,%1}, %2;" : "=f"(f.x), "=f"(f.y) : "l"(v)); return f;
}
__device__ __forceinline__ ull ffma2(ull a, ull b, ull c) {
    ull d; asm("fma.rn.f32x2 %0, %1, %2, %3;" : "=l"(d) : "l"(a), "l"(b), "l"(c)); return d;
}
__device__ __forceinline__ ull fadd2(ull a, ull b) {
    ull d; asm("add.rn.f32x2 %0, %1, %2;" : "=l"(d) : "l"(a), "l"(b)); return d;
}

// HW tanh (single MUFU op); validated rel_err ~7e-7 end-to-end
__device__ __forceinline__ float tanh_fast(float x) {
    float y; asm("tanh.approx.f32 %0, %1;" : "=f"(y) : "f"(x)); return y;
}
__device__ __forceinline__ float sig_fast(float x) {
    return fmaf(0.5f, tanh_fast(0.5f * x), 0.5f);
}
__device__ __forceinline__ float sigmoidf_acc(float x) {
    return __fdividef(1.f, 1.f + __expf(-x));
}

#define B_  256
#define S_  1024
#define F_  64
#define H_  64
#define G_  256   // 4*H

// h scratch: [b][t][u] floats. 64MB. (g_xz is GONE — z flows through smem.)
__device__ float g_h[(size_t)B_ * S_ * H_];

// =====================================================================
// FUSED kernel: input projection + LSTM recurrence.
// 128 CTAs x 384 thr (1 CTA/SM uniform). CTA owns 2 batch rows.
//   warps 0-7  (tid<256): CONSUMERS — round-7 recurrence.
//        tid = r*128+p, pair p -> u=p>>1, s=p&1,
//        s=0:(z_i,z_f) cols (u,u+64); s=1:(z_c,z_o) cols (u+128,u+192).
//   warps 8-11 (tid>=256): PRODUCERS — pair p = tid&127, SAME column
//        mapping but with `kernel` weights; compute z(t+2) for both rows
//        into zring; stream x via xring (p<64 threads load).
// One __syncthreads per step. Ring distances: z written t-2; x written t-1.
// =====================================================================
__global__ void __launch_bounds__(384, 1) lstm_fused(
    const float* __restrict__ x, const float* __restrict__ kern,
    const float* __restrict__ rec, const float* __restrict__ bias)
{
    const int tid    = threadIdx.x;
    const bool isProd = (tid >= 256);
    const int p    = tid & 127;
    const int r    = (tid >> 7) & 1;      // consumer row (producers: 0, unused)
    const int u    = p >> 1;
    const int s    = p & 1;
    const int c0   = u + (s ? 128 : 0);
    const int c1   = c0 + 64;

    // role-dependent weight source, SAME register layout (shared allocation)
    const float* wsrc = isProd ? kern : rec;
    ull wA[32], wB[32];
#pragma unroll
    for (int m = 0; m < 32; m++) {
        wA[m] = pack2(wsrc[(2 * m) * G_ + c0], wsrc[(2 * m + 1) * G_ + c0]);
        wB[m] = pack2(wsrc[(2 * m) * G_ + c1], wsrc[(2 * m + 1) * G_ + c1]);
    }
    const float bc0 = bias[c0], bc1 = bias[c1];

    __shared__ __align__(16) ull hpk[2][2][32];    // [parity][row][m] h pairs
    __shared__ __align__(16) ull xring[4][2][32];  // [slot][row][kpair] x pairs
    __shared__ __align__(16) ull zring[4][2][128]; // [slot][row][pair] (z_c0,z_c1)

    if (tid < 64) hpk[1][tid >> 5][tid & 31] = 0ull;   // h(-1)=0 at parity 1

    const int brow0 = blockIdx.x * 2;
    float c = 0.f;
    float* hout = g_h + (size_t)(brow0 + r) * S_ * H_ + u;

    // ---- producer x-stream setup (threads p<64 of producer warps) ----
    const int lr = p >> 5;       // row 0/1 (for p<64)
    const int lm = p & 31;       // k-pair
    const float* xbase = x + (size_t)(brow0 + lr) * S_ * F_ + 2 * lm;
    float2 vold  = make_float2(0.f, 0.f);
    float2 vold2 = make_float2(0.f, 0.f);

    if (isProd && p < 64) {
        float2 t0 = *(const float2*)(xbase + 0 * F_);
        xring[0][lr][lm] = pack2(t0.x, t0.y);
        float2 t1 = *(const float2*)(xbase + 1 * F_);
        xring[1][lr][lm] = pack2(t1.x, t1.y);
        float2 t2 = *(const float2*)(xbase + 2 * F_);
        xring[2][lr][lm] = pack2(t2.x, t2.y);
        vold  = *(const float2*)(xbase + 3 * F_);
        vold2 = *(const float2*)(xbase + 4 * F_);
    }
    __syncthreads();

    // ---- prologue: producers compute z(0), z(1) ----
    if (isProd) {
#pragma unroll
        for (int k = 0; k < 2; k++) {
            const ull* xr0 = xring[k][0];
            const ull* xr1 = xring[k][1];
            ull a0 = 0, a1 = 0, a2 = 0, a3 = 0;
            ull b0 = 0, b1 = 0, b2 = 0, b3 = 0;
#pragma unroll
            for (int m = 0; m < 32; m += 2) {
                const ull x00 = xr0[m], x01 = xr0[m + 1];
                const ull x10 = xr1[m], x11 = xr1[m + 1];
                a0 = ffma2(wA[m], x00, a0); a1 = ffma2(wA[m + 1], x01, a1);
                a2 = ffma2(wB[m], x00, a2); a3 = ffma2(wB[m + 1], x01, a3);
                b0 = ffma2(wA[m], x10, b0); b1 = ffma2(wA[m + 1], x11, b1);
                b2 = ffma2(wB[m], x10, b2); b3 = ffma2(wB[m + 1], x11, b3);
            }
            const float2 r0a = unpack2(fadd2(a0, a1));
            const float2 r0b = unpack2(fadd2(a2, a3));
            const float2 r1a = unpack2(fadd2(b0, b1));
            const float2 r1b = unpack2(fadd2(b2, b3));
            zring[k][0][p] = pack2(bc0 + r0a.x + r0a.y, bc1 + r0b.x + r0b.y);
            zring[k][1][p] = pack2(bc0 + r1a.x + r1a.y, bc1 + r1b.x + r1b.y);
        }
    }
    __syncthreads();

    // =================== main loop: one barrier per step ===================
#pragma unroll 2
    for (int t = 0; t < S_; t++) {
        if (!isProd) {
            // -------- CONSUMER: round-7 recurrence, z from shared --------
            const ull zcur = zring[t & 3][r][p];
            const ull* hp  = hpk[(t & 1) ^ 1][r];

            ull a0 = 0, a1 = 0, a2 = 0, a3 = 0;
            ull b0 = 0, b1 = 0, b2 = 0, b3 = 0;
#pragma unroll
            for (int m = 0; m < 32; m += 4) {
                const ull h0 = hp[m],     h1 = hp[m + 1];
                const ull h2 = hp[m + 2], h3 = hp[m + 3];
                a0 = ffma2(wA[m],     h0, a0);
                a1 = ffma2(wA[m + 1], h1, a1);
                a2 = ffma2(wB[m],     h0, a2);
                a3 = ffma2(wB[m + 1], h1, a3);
                b0 = ffma2(wA[m + 2], h2, b0);
                b1 = ffma2(wA[m + 3], h3, b1);
                b2 = ffma2(wB[m + 2], h2, b2);
                b3 = ffma2(wB[m + 3], h3, b3);
            }
            const float2 sa  = unpack2(fadd2(fadd2(a0, a1), fadd2(b0, b1)));
            const float2 sb  = unpack2(fadd2(fadd2(a2, a3), fadd2(b2, b3)));
            const float2 zin = unpack2(zcur);
            const float zv0 = zin.x + sa.x + sa.y;   // z_i (s=0) / z_c (s=1)
            const float zv1 = zin.y + sb.x + sb.y;   // z_f (s=0) / z_o (s=1)

            const float g0 = s ? tanh_fast(zv0) : sig_fast(zv0);
            const float g1 = sig_fast(zv1);
            const float t0 = __shfl_xor_sync(0xffffffffu, g0, 1);
            const float t1 = __shfl_xor_sync(0xffffffffu, g1, 1);

            if (s == 0) {                  // lane holds (i,f); partner sent (tc,o)
                c = fmaf(g1, c, g0 * t0);
                const float h = t1 * tanh_fast(c);
                ((float*)hpk[t & 1][r])[u] = h;    // publish h(t)
                hout[(size_t)t * H_] = h;          // stream for head kernel
            }
        } else {
            // -------- PRODUCER: x stream + z(t+2) --------
            if (p < 64) {
                if (t + 3 < S_) xring[(t + 3) & 3][lr][lm] = pack2(vold.x, vold.y);
                vold = vold2;
                if (t + 5 < S_) vold2 = *(const float2*)(xbase + (size_t)(t + 5) * F_);
            }
            if (t + 2 < S_) {
                const int  sl  = (t + 2) & 3;
                const ull* xr0 = xring[sl][0];
                const ull* xr1 = xring[sl][1];
                ull a0 = 0, a1 = 0, a2 = 0, a3 = 0;
                ull b0 = 0, b1 = 0, b2 = 0, b3 = 0;
#pragma unroll
                for (int m = 0; m < 32; m += 2) {
                    const ull x00 = xr0[m], x01 = xr0[m + 1];
                    const ull x10 = xr1[m], x11 = xr1[m + 1];
                    a0 = ffma2(wA[m], x00, a0); a1 = ffma2(wA[m + 1], x01, a1);
                    a2 = ffma2(wB[m], x00, a2); a3 = ffma2(wB[m + 1], x01, a3);
                    b0 = ffma2(wA[m], x10, b0); b1 = ffma2(wA[m + 1], x11, b1);
                    b2 = ffma2(wB[m], x10, b2); b3 = ffma2(wB[m + 1], x11, b3);
                }
                const float2 r0a = unpack2(fadd2(a0, a1));
                const float2 r0b = unpack2(fadd2(a2, a3));
                const float2 r1a = unpack2(fadd2(b0, b1));
                const float2 r1b = unpack2(fadd2(b2, b3));
                zring[sl][0][p] = pack2(bc0 + r0a.x + r0a.y, bc1 + r0b.x + r0b.y);
                zring[sl][1][p] = pack2(bc0 + r1a.x + r1a.y, bc1 + r1b.x + r1b.y);
            }
        }
        __syncthreads();                    // the ONLY barrier per step
    }
}

// =====================================================================
// Dense head: out[b,t] = sigmoid(h[b,t,:]·dw + db). One warp per output.
// =====================================================================
__global__ void __launch_bounds__(256, 4) lstm_head(
    const float* __restrict__ dw, const float* __restrict__ db,
    float* __restrict__ out)
{
    const int lane = threadIdx.x & 31;
    const int o    = blockIdx.x * 8 + (threadIdx.x >> 5);   // output index b*S+t

    const float2 hv = *(const float2*)(g_h + (size_t)o * H_ + 2 * lane);
    const float2 wv = *(const float2*)(dw + 2 * lane);
    float pd = hv.x * wv.x + hv.y * wv.y;
#pragma unroll
    for (int off = 16; off; off >>= 1)
        pd += __shfl_xor_sync(0xffffffffu, pd, off);
    if (lane == 0)
        out[o] = sigmoidf_acc(pd + db[0]);
}

// =====================================================================
extern "C" void kernel_launch(void* const* d_in, const int* in_sizes, int n_in,
                              void* d_out, int out_size)
{
    const float* x    = (const float*)d_in[0];  // [256,1024,64]
    const float* kern = (const float*)d_in[1];  // [64,256]
    const float* rec  = (const float*)d_in[2];  // [64,256]
    const float* bias = (const float*)d_in[3];  // [256]
    const float* dw   = (const float*)d_in[4];  // [64,1]
    const float* db   = (const float*)d_in[5];  // [1]
    float* out = (float*)d_out;                 // [256,1024,1]

    lstm_fused<<<128, 384>>>(x, kern, rec, bias);
    lstm_head<<<(B_ * S_) / 8, 256>>>(dw, db, out);
}

// round 14
// speedup vs baseline: 1.9366x; 1.9366x over previous
#include <cuda_runtime.h>

typedef unsigned long long ull;

// ---------------- packed f32x2 helpers (Blackwell FFMA2 path) ----------------
__device__ __forceinline__ ull pack2(float a, float b) {
    ull r; asm("mov.b64 %0, {%1,%2};" : "=l"(r) : "f"(a), "f"(b)); return r;
}
__device__ __forceinline__ float2 unpack2(ull v) {
    float2 f; asm("mov.b64 {%0,%1}, %2;" : "=f"(f.x), "=f"(f.y) : "l"(v)); return f;
}
__device__ __forceinline__ ull ffma2(ull a, ull b, ull c) {
    ull d; asm("fma.rn.f32x2 %0, %1, %2, %3;" : "=l"(d) : "l"(a), "l"(b), "l"(c)); return d;
}
__device__ __forceinline__ ull fadd2(ull a, ull b) {
    ull d; asm("add.rn.f32x2 %0, %1, %2;" : "=l"(d) : "l"(a), "l"(b)); return d;
}

// HW tanh (single MUFU op); validated rel_err ~7e-7 end-to-end
__device__ __forceinline__ float tanh_fast(float x) {
    float y; asm("tanh.approx.f32 %0, %1;" : "=f"(y) : "f"(x)); return y;
}
__device__ __forceinline__ float sig_fast(float x) {
    return fmaf(0.5f, tanh_fast(0.5f * x), 0.5f);
}
__device__ __forceinline__ float sigmoidf_acc(float x) {
    return __fdividef(1.f, 1.f + __expf(-x));
}

#define B_  256
#define S_  1024
#define F_  64
#define H_  64
#define G_  256   // 4*H

// Pair mapping: pair index p -> u = p>>1, s = p&1
//   s=0: columns (u,     u+64 ) = (z_i[u],  z_f[u])
//   s=1: columns (u+128, u+192) = (z_c[u],  z_o[u])
// xz scratch: [t][b][p] packed float2 (col c0, col c1). 268MB.
__device__ ull   g_xz[(size_t)S_ * B_ * 128];
// h scratch: [b][t][u] floats. 64MB.
__device__ float g_h[(size_t)B_ * S_ * H_];

// =====================================================================
// Kernel A: xz = x @ kernel + bias — round-7 structure; x ring held as
// NATIVE ulonglong2 so reads are LDS.128 (half the LDS issues).
// 1024 CTAs x 256 thr; per iter one quad (4 rows); 64 iters.
// =====================================================================
__global__ void __launch_bounds__(256, 1) lstm_xgemm(
    const float* __restrict__ x, const float* __restrict__ kern,
    const float* __restrict__ bias)
{
    const int tid  = threadIdx.x;
    const int j    = tid & 127;
    const int half = tid >> 7;
    const int u    = j >> 1;
    const int s    = j & 1;
    const int c0   = u + (s ? 128 : 0);
    const int c1   = c0 + 64;

    // k-packed weights for own two columns: 64 ull = 128 regs
    ull wA[32], wB[32];
#pragma unroll
    for (int m = 0; m < 32; m++) {
        wA[m] = pack2(kern[(2 * m) * G_ + c0], kern[(2 * m + 1) * G_ + c0]);
        wB[m] = pack2(kern[(2 * m) * G_ + c1], kern[(2 * m + 1) * G_ + c1]);
    }
    const float bc0 = bias[c0], bc1 = bias[c1];

    // [slot][row][kquad]: element holds k-pairs (2q, 2q+1) => 4 k values
    __shared__ __align__(16) ulonglong2 xpk[4][4][16];

    const int lr = (tid >> 5) & 3;   // loader row within quad
    const int lm = tid & 31;         // loader k-pair
    const int qbase = blockIdx.x * 64;

    float2 v = make_float2(0.f, 0.f);
    if (tid < 128) {
        float2 t0 = *(const float2*)(x + (size_t)((qbase + 0) * 4 + lr) * F_ + 2 * lm);
        ((ull*)xpk[0][lr])[lm] = pack2(t0.x, t0.y);
        float2 t1 = *(const float2*)(x + (size_t)((qbase + 1) * 4 + lr) * F_ + 2 * lm);
        ((ull*)xpk[1][lr])[lm] = pack2(t1.x, t1.y);
        v = *(const float2*)(x + (size_t)((qbase + 2) * 4 + lr) * F_ + 2 * lm);
    }
    __syncthreads();

#pragma unroll 4
    for (int i = 0; i < 64; i++) {
        if (tid < 128 && i + 2 < 64) {
            ((ull*)xpk[(i + 2) & 3][lr])[lm] = pack2(v.x, v.y);
            if (i + 3 < 64)
                v = *(const float2*)(x + (size_t)((qbase + i + 3) * 4 + lr) * F_ + 2 * lm);
        }

        const ulonglong2* xa = xpk[i & 3][half];       // row n0
        const ulonglong2* xb = xpk[i & 3][half + 2];   // row n0+2
        ull a0 = 0, a1 = 0, a2 = 0, a3 = 0;            // row A, cols c0/c1
        ull b0 = 0, b1 = 0, b2 = 0, b3 = 0;            // row B
#pragma unroll
        for (int m2 = 0; m2 < 16; m2++) {
            const ulonglong2 va = xa[m2];   // LDS.128: k-pairs (2m2, 2m2+1)
            const ulonglong2 vb = xb[m2];
            a0 = ffma2(wA[2 * m2],     va.x, a0);
            a1 = ffma2(wA[2 * m2 + 1], va.y, a1);
            a2 = ffma2(wB[2 * m2],     va.x, a2);
            a3 = ffma2(wB[2 * m2 + 1], va.y, a3);
            b0 = ffma2(wA[2 * m2],     vb.x, b0);
            b1 = ffma2(wA[2 * m2 + 1], vb.y, b1);
            b2 = ffma2(wB[2 * m2],     vb.x, b2);
            b3 = ffma2(wB[2 * m2 + 1], vb.y, b3);
        }
        const float2 sa0 = unpack2(fadd2(a0, a1));
        const float2 sa1 = unpack2(fadd2(a2, a3));
        const float2 sb0 = unpack2(fadd2(b0, b1));
        const float2 sb1 = unpack2(fadd2(b2, b3));
        const ull r0 = pack2(bc0 + sa0.x + sa0.y, bc1 + sa1.x + sa1.y);
        const ull r1 = pack2(bc0 + sb0.x + sb0.y, bc1 + sb1.x + sb1.y);

        const int n0 = (qbase + i) * 4 + half;   // global row = b*S + t
        const int n1 = n0 + 2;
        {
            const int bb = n0 >> 10, tt = n0 & 1023;
            g_xz[((size_t)tt * B_ + bb) * 128 + j] = r0;
        }
        {
            const int bb = n1 >> 10, tt = n1 & 1023;
            g_xz[((size_t)tt * B_ + bb) * 128 + j] = r1;
        }
        __syncthreads();
    }
}

// =====================================================================
// Kernel B: LSTM recurrence — round-7 structure VERBATIM, but h buffer
// held as NATIVE ulonglong2 so matvec reads are LDS.128 (16 per step).
// 128 CTAs x 256 thr (2 rows/CTA, uniform 1 CTA/SM), named bar per row,
// depth-8 z register ring, 8 FFMA2 chains, h streamed to g_h.
// =====================================================================
__global__ void __launch_bounds__(256, 1) lstm_recur(
    const float* __restrict__ rec)
{
    const int tid  = threadIdx.x;
    const int p    = tid & 127;
    const int r    = tid >> 7;
    const int u    = p >> 1;
    const int s    = p & 1;
    const int brow = blockIdx.x * 2 + r;
    const int c0   = u + (s ? 128 : 0);
    const int c1   = c0 + 64;

    ull wA[32], wB[32];
#pragma unroll
    for (int m = 0; m < 32; m++) {
        wA[m] = pack2(rec[(2 * m) * G_ + c0], rec[(2 * m + 1) * G_ + c0]);
        wB[m] = pack2(rec[(2 * m) * G_ + c1], rec[(2 * m + 1) * G_ + c1]);
    }

    // [parity][row][kquad]: element = h-pairs (2q, 2q+1) = 4 h values
    __shared__ __align__(16) ulonglong2 hpk[2][2][16];

    if (tid < 32)                                   // h(-1) = 0 at parity 1
        hpk[1][tid >> 4][tid & 15] = make_ulonglong2(0ull, 0ull);

    float c = 0.f;
    const size_t ZS = (size_t)B_ * 128;
    const ull* zp = g_xz + (size_t)brow * 128 + p;
    float* hout = g_h + (size_t)brow * S_ * H_ + u;    // [t][u] stream

    // depth-8 z prefetch ring
    ull zr[8];
#pragma unroll
    for (int d = 0; d < 8; d++) zr[d] = zp[(size_t)d * ZS];
    zp += 8 * ZS;
    __syncthreads();

    const int barid = r + 1;     // named barrier per row (128 threads each)

#pragma unroll 8
    for (int t = 0; t < S_; t++) {
        const int pr = (t & 1) ^ 1;                 // parity holding h(t-1)
        const ulonglong2* hp = hpk[pr][r];

        const ull zcur = zr[t & 7];                 // z issued 8 steps ago
        if (t + 8 < S_) zr[t & 7] = *zp;
        zp += ZS;

        // matvec: 16 broadcast LDS.128 + 64 FFMA2, 8 chains
        ull a0 = 0, a1 = 0, a2 = 0, a3 = 0;
        ull b0 = 0, b1 = 0, b2 = 0, b3 = 0;
#pragma unroll
        for (int m2 = 0; m2 < 16; m2 += 2) {
            const ulonglong2 hA = hp[m2];           // k-pairs (2m2, 2m2+1)
            const ulonglong2 hB = hp[m2 + 1];       // k-pairs (2m2+2, 2m2+3)
            a0 = ffma2(wA[2 * m2],     hA.x, a0);
            a1 = ffma2(wA[2 * m2 + 1], hA.y, a1);
            a2 = ffma2(wB[2 * m2],     hA.x, a2);
            a3 = ffma2(wB[2 * m2 + 1], hA.y, a3);
            b0 = ffma2(wA[2 * m2 + 2], hB.x, b0);
            b1 = ffma2(wA[2 * m2 + 3], hB.y, b1);
            b2 = ffma2(wB[2 * m2 + 2], hB.x, b2);
            b3 = ffma2(wB[2 * m2 + 3], hB.y, b3);
        }
        const float2 sa  = unpack2(fadd2(fadd2(a0, a1), fadd2(b0, b1)));
        const float2 sb  = unpack2(fadd2(fadd2(a2, a3), fadd2(b2, b3)));
        const float2 zin = unpack2(zcur);
        const float zv0 = zin.x + sa.x + sa.y;      // z_i (s=0) / z_c (s=1)
        const float zv1 = zin.y + sb.x + sb.y;      // z_f (s=0) / z_o (s=1)

        // own activations, then in-warp exchange with partner lane
        const float g0 = s ? tanh_fast(zv0) : sig_fast(zv0);
        const float g1 = sig_fast(zv1);
        const float t0 = __shfl_xor_sync(0xffffffffu, g0, 1);
        const float t1 = __shfl_xor_sync(0xffffffffu, g1, 1);

        if (s == 0) {                               // lane holds (i,f); partner sent (tc,o)
            c = fmaf(g1, c, g0 * t0);
            const float h = t1 * tanh_fast(c);
            ((float*)hpk[t & 1][r])[u] = h;         // publish h_u(t)
            hout[(size_t)t * H_] = h;               // stream to gmem (off-chain STG)
        }
        asm volatile("bar.sync %0, 128;" :: "r"(barid) : "memory");
    }
}

// =====================================================================
// Kernel C: dense head  out[b,t] = sigmoid(h[b,t,:]·dw + db)
// One warp per output, coalesced float2 loads, shfl reduce.
// =====================================================================
__global__ void __launch_bounds__(256, 4) lstm_head(
    const float* __restrict__ dw, const float* __restrict__ db,
    float* __restrict__ out)
{
    const int lane = threadIdx.x & 31;
    const int o    = blockIdx.x * 8 + (threadIdx.x >> 5);   // output index b*S+t

    const float2 hv = *(const float2*)(g_h + (size_t)o * H_ + 2 * lane);
    const float2 wv = *(const float2*)(dw + 2 * lane);
    float pd = hv.x * wv.x + hv.y * wv.y;
#pragma unroll
    for (int off = 16; off; off >>= 1)
        pd += __shfl_xor_sync(0xffffffffu, pd, off);
    if (lane == 0)
        out[o] = sigmoidf_acc(pd + db[0]);
}

// =====================================================================
extern "C" void kernel_launch(void* const* d_in, const int* in_sizes, int n_in,
                              void* d_out, int out_size)
{
    const float* x    = (const float*)d_in[0];  // [256,1024,64]
    const float* kern = (const float*)d_in[1];  // [64,256]
    const float* rec  = (const float*)d_in[2];  // [64,256]
    const float* bias = (const float*)d_in[3];  // [256]
    const float* dw   = (const float*)d_in[4];  // [64,1]
    const float* db   = (const float*)d_in[5];  // [1]
    float* out = (float*)d_out;                 // [256,1024,1]

    lstm_xgemm<<<1024, 256>>>(x, kern, bias);
    lstm_recur<<<128, 256>>>(rec);
    lstm_head<<<(B_ * S_) / 8, 256>>>(dw, db, out);
}